// round 3
// baseline (speedup 1.0000x reference)
#include <cuda_runtime.h>
#include <cstdint>

#define BB   2048
#define TT   64
#define DD   256
#define HH   256
#define CC   1000
#define SS   26
#define DCC  1256   // D + C
#define MROWS 16    // batch rows per recurrence CTA

// Scratch (allocation-free: __device__ globals)
__device__ float g_Hproj[(size_t)BB * TT * HH];    // 128 MB
__device__ float g_hidden[(size_t)BB * SS * HH];   // 52 MB

__device__ __forceinline__ float ftanh(float x) {
    float y;
    asm("tanh.approx.f32 %0, %1;" : "=f"(y) : "f"(x));
    return y;
}
__device__ __forceinline__ float fsig(float x) {
    return 0.5f * ftanh(0.5f * x) + 0.5f;
}

// ---------------------------------------------------------------------------
// Kernel A: H_proj[b,t,h] = sum_d batch_H[b,t,d] * W_i2h[h,d]
// GEMM M=B*T=131072, N=256, K=256. BM=BN=64, BK=16, 256 threads, 4x4 micro.
// ---------------------------------------------------------------------------
__global__ void __launch_bounds__(256) hproj_kernel(
    const float* __restrict__ A, const float* __restrict__ W)
{
    __shared__ float As[16][68];
    __shared__ float Ws[16][68];
    const int bm = blockIdx.x * 64;
    const int bn = blockIdx.y * 64;
    const int tid = threadIdx.x;
    const int tx = tid & 15, ty = tid >> 4;
    const int lr = tid >> 2;           // 0..63
    const int lk = (tid & 3) << 2;     // 0,4,8,12

    float acc[4][4] = {};
    for (int k0 = 0; k0 < DD; k0 += 16) {
        float4 av = *(const float4*)(A + (size_t)(bm + lr) * DD + k0 + lk);
        float4 wv = *(const float4*)(W + (size_t)(bn + lr) * DD + k0 + lk);
        As[lk + 0][lr] = av.x; As[lk + 1][lr] = av.y;
        As[lk + 2][lr] = av.z; As[lk + 3][lr] = av.w;
        Ws[lk + 0][lr] = wv.x; Ws[lk + 1][lr] = wv.y;
        Ws[lk + 2][lr] = wv.z; Ws[lk + 3][lr] = wv.w;
        __syncthreads();
        #pragma unroll
        for (int kk = 0; kk < 16; kk++) {
            float a[4], w[4];
            #pragma unroll
            for (int i = 0; i < 4; i++) a[i] = As[kk][ty * 4 + i];
            #pragma unroll
            for (int j = 0; j < 4; j++) w[j] = Ws[kk][tx * 4 + j];
            #pragma unroll
            for (int i = 0; i < 4; i++)
                #pragma unroll
                for (int j = 0; j < 4; j++)
                    acc[i][j] += a[i] * w[j];
        }
        __syncthreads();
    }
    #pragma unroll
    for (int i = 0; i < 4; i++) {
        float4 v = make_float4(acc[i][0], acc[i][1], acc[i][2], acc[i][3]);
        *(float4*)(g_Hproj + (size_t)(bm + ty * 4 + i) * HH + bn + tx * 4) = v;
    }
}

// ---------------------------------------------------------------------------
// Kernel B: persistent recurrence. grid=128 CTAs, 256 threads, M=16 rows/CTA.
// ---------------------------------------------------------------------------
__global__ void __launch_bounds__(256) recur_kernel(
    const float* __restrict__ batch_H, const int* __restrict__ text,
    const float* __restrict__ W_h2h,  const float* __restrict__ b_h2h,
    const float* __restrict__ W_score,
    const float* __restrict__ W_ih,   const float* __restrict__ W_hh,
    const float* __restrict__ b_ih,   const float* __restrict__ b_hh)
{
    extern __shared__ float sm[];
    float* sh_h   = sm;                      // 16*256
    float* sh_c   = sh_h   + MROWS * HH;     // 16*256
    float* sh_hp  = sh_c   + MROWS * HH;     // 16*256
    float* sh_ctx = sh_hp  + MROWS * HH;     // 16*256
    float* sh_e   = sh_ctx + MROWS * HH;     // 16*64 (scores, then alpha)
    float* sh_ws  = sh_e   + MROWS * TT;     // 256
    int*   sh_ch  = (int*)(sh_ws + HH);      // 16

    const int tid  = threadIdx.x;
    const int warp = tid >> 5, lane = tid & 31;
    const int r0   = blockIdx.x * MROWS;

    for (int i = tid; i < MROWS * HH; i += 256) { sh_h[i] = 0.f; sh_c[i] = 0.f; }
    sh_ws[tid] = W_score[tid];
    __syncthreads();

    for (int s = 0; s < SS; s++) {
        if (tid < MROWS) sh_ch[tid] = text[(r0 + tid) * SS + s];

        // ---- Stage 1: hp = h @ W_h2h^T + b_h2h. thread = output unit n ----
        {
            const int n = tid;
            float acc[MROWS];
            const float bb = b_h2h[n];
            #pragma unroll
            for (int m = 0; m < MROWS; m++) acc[m] = bb;
            const float4* wr = (const float4*)(W_h2h + (size_t)n * HH);
            #pragma unroll 2
            for (int k4 = 0; k4 < HH / 4; k4++) {
                float4 w = wr[k4];
                #pragma unroll
                for (int m = 0; m < MROWS; m++) {
                    float4 hv = *(const float4*)(sh_h + m * HH + k4 * 4);
                    acc[m] += w.x * hv.x + w.y * hv.y + w.z * hv.z + w.w * hv.w;
                }
            }
            #pragma unroll
            for (int m = 0; m < MROWS; m++) sh_hp[m * HH + n] = acc[m];
        }
        __syncthreads();

        // ---- Stage 2: e[m,t] = Wscore . tanh(Hproj[m,t,:] + hp[m,:]) ------
        for (int p = warp; p < MROWS * TT; p += 8) {
            const int m = p >> 6, t = p & 63;
            const float* hp = sh_hp + m * HH;
            const float* hx = g_Hproj + ((size_t)(r0 + m) * TT + t) * HH;
            float sum = 0.f;
            #pragma unroll
            for (int i = 0; i < 2; i++) {
                int h0 = i * 128 + lane * 4;
                float4 a = *(const float4*)(hx + h0);
                float4 b = *(const float4*)(hp + h0);
                float4 w = *(const float4*)(sh_ws + h0);
                sum += w.x * ftanh(a.x + b.x) + w.y * ftanh(a.y + b.y)
                     + w.z * ftanh(a.z + b.z) + w.w * ftanh(a.w + b.w);
            }
            #pragma unroll
            for (int o = 16; o > 0; o >>= 1) sum += __shfl_xor_sync(0xffffffffu, sum, o);
            if (lane == 0) sh_e[p] = sum;
        }
        __syncthreads();

        // ---- Stage 3: softmax over t (warp handles 2 rows) ----------------
        #pragma unroll
        for (int mm = 0; mm < 2; mm++) {
            const int m = warp * 2 + mm;
            float e0 = sh_e[m * TT + lane];
            float e1 = sh_e[m * TT + 32 + lane];
            float mx = fmaxf(e0, e1);
            #pragma unroll
            for (int o = 16; o > 0; o >>= 1) mx = fmaxf(mx, __shfl_xor_sync(0xffffffffu, mx, o));
            float x0 = __expf(e0 - mx), x1 = __expf(e1 - mx);
            float sume = x0 + x1;
            #pragma unroll
            for (int o = 16; o > 0; o >>= 1) sume += __shfl_xor_sync(0xffffffffu, sume, o);
            float inv = __frcp_rn(sume);
            sh_e[m * TT + lane]      = x0 * inv;
            sh_e[m * TT + 32 + lane] = x1 * inv;
        }
        __syncthreads();

        // ---- Stage 4: context[m,d] = sum_t alpha[m,t] * batch_H[m,t,d] ----
        {
            const int d = tid;
            for (int m = 0; m < MROWS; m++) {
                const float* bh = batch_H + (size_t)(r0 + m) * TT * DD + d;
                float acc = 0.f;
                #pragma unroll 8
                for (int t = 0; t < TT; t++) acc += sh_e[m * TT + t] * bh[t * DD];
                sh_ctx[m * HH + d] = acc;
            }
        }
        __syncthreads();

        // ---- Stage 5: gates + LSTM. thread = unit n, 4 gate rows ----------
        {
            const int n = tid;
            const float* wi0 = W_ih + (size_t)(n      ) * DCC;
            const float* wi1 = W_ih + (size_t)(n + 256) * DCC;
            const float* wi2 = W_ih + (size_t)(n + 512) * DCC;
            const float* wi3 = W_ih + (size_t)(n + 768) * DCC;
            const float bi0 = b_ih[n      ] + b_hh[n      ];
            const float bi1 = b_ih[n + 256] + b_hh[n + 256];
            const float bi2 = b_ih[n + 512] + b_hh[n + 512];
            const float bi3 = b_ih[n + 768] + b_hh[n + 768];

            float a0[MROWS], a1[MROWS], a2[MROWS], a3[MROWS];
            #pragma unroll
            for (int m = 0; m < MROWS; m++) {
                const int ch = 256 + sh_ch[m];   // one-hot => column gather
                a0[m] = bi0 + wi0[ch];
                a1[m] = bi1 + wi1[ch];
                a2[m] = bi2 + wi2[ch];
                a3[m] = bi3 + wi3[ch];
            }
            // context @ W_ih[:, :256]^T
            #pragma unroll 2
            for (int k4 = 0; k4 < DD / 4; k4++) {
                float4 w0 = *(const float4*)(wi0 + k4 * 4);
                float4 w1 = *(const float4*)(wi1 + k4 * 4);
                float4 w2 = *(const float4*)(wi2 + k4 * 4);
                float4 w3 = *(const float4*)(wi3 + k4 * 4);
                #pragma unroll
                for (int m = 0; m < MROWS; m++) {
                    float4 x = *(const float4*)(sh_ctx + m * HH + k4 * 4);
                    a0[m] += w0.x * x.x + w0.y * x.y + w0.z * x.z + w0.w * x.w;
                    a1[m] += w1.x * x.x + w1.y * x.y + w1.z * x.z + w1.w * x.w;
                    a2[m] += w2.x * x.x + w2.y * x.y + w2.z * x.z + w2.w * x.w;
                    a3[m] += w3.x * x.x + w3.y * x.y + w3.z * x.z + w3.w * x.w;
                }
            }
            // h @ W_hh^T
            const float* wh0 = W_hh + (size_t)(n      ) * HH;
            const float* wh1 = W_hh + (size_t)(n + 256) * HH;
            const float* wh2 = W_hh + (size_t)(n + 512) * HH;
            const float* wh3 = W_hh + (size_t)(n + 768) * HH;
            #pragma unroll 2
            for (int k4 = 0; k4 < HH / 4; k4++) {
                float4 w0 = *(const float4*)(wh0 + k4 * 4);
                float4 w1 = *(const float4*)(wh1 + k4 * 4);
                float4 w2 = *(const float4*)(wh2 + k4 * 4);
                float4 w3 = *(const float4*)(wh3 + k4 * 4);
                #pragma unroll
                for (int m = 0; m < MROWS; m++) {
                    float4 x = *(const float4*)(sh_h + m * HH + k4 * 4);
                    a0[m] += w0.x * x.x + w0.y * x.y + w0.z * x.z + w0.w * x.w;
                    a1[m] += w1.x * x.x + w1.y * x.y + w1.z * x.z + w1.w * x.w;
                    a2[m] += w2.x * x.x + w2.y * x.y + w2.z * x.z + w2.w * x.w;
                    a3[m] += w3.x * x.x + w3.y * x.y + w3.z * x.z + w3.w * x.w;
                }
            }
            // LSTM update (gate order i,f,g,o). sh_c[m][n] is private to thread n.
            float hn[MROWS];
            #pragma unroll
            for (int m = 0; m < MROWS; m++) {
                const float cprev = sh_c[m * HH + n];
                const float cnew  = fsig(a1[m]) * cprev + fsig(a0[m]) * ftanh(a2[m]);
                const float hnew  = fsig(a3[m]) * ftanh(cnew);
                sh_c[m * HH + n] = cnew;
                hn[m] = hnew;
                g_hidden[((size_t)(r0 + m) * SS + s) * HH + n] = hnew;
            }
            __syncthreads();   // all reads of sh_h done before overwrite
            #pragma unroll
            for (int m = 0; m < MROWS; m++) sh_h[m * HH + n] = hn[m];
        }
        __syncthreads();
    }
}

// ---------------------------------------------------------------------------
// Kernel C: probs[m,n] = g_hidden[m,:] . W_gen[n,:] + b_gen[n]
// GEMM M=B*S=53248, N=1000, K=256.
// ---------------------------------------------------------------------------
__global__ void __launch_bounds__(256) gen_kernel(
    const float* __restrict__ Wg, const float* __restrict__ bg,
    float* __restrict__ out)
{
    __shared__ float As[16][68];
    __shared__ float Ws[16][68];
    const int bm = blockIdx.x * 64;
    const int bn = blockIdx.y * 64;
    const int tid = threadIdx.x;
    const int tx = tid & 15, ty = tid >> 4;
    const int lr = tid >> 2;
    const int lk = (tid & 3) << 2;

    float acc[4][4] = {};
    for (int k0 = 0; k0 < HH; k0 += 16) {
        float4 av = *(const float4*)(g_hidden + (size_t)(bm + lr) * HH + k0 + lk);
        float4 wv = make_float4(0.f, 0.f, 0.f, 0.f);
        if (bn + lr < CC)
            wv = *(const float4*)(Wg + (size_t)(bn + lr) * HH + k0 + lk);
        As[lk + 0][lr] = av.x; As[lk + 1][lr] = av.y;
        As[lk + 2][lr] = av.z; As[lk + 3][lr] = av.w;
        Ws[lk + 0][lr] = wv.x; Ws[lk + 1][lr] = wv.y;
        Ws[lk + 2][lr] = wv.z; Ws[lk + 3][lr] = wv.w;
        __syncthreads();
        #pragma unroll
        for (int kk = 0; kk < 16; kk++) {
            float a[4], w[4];
            #pragma unroll
            for (int i = 0; i < 4; i++) a[i] = As[kk][ty * 4 + i];
            #pragma unroll
            for (int j = 0; j < 4; j++) w[j] = Ws[kk][tx * 4 + j];
            #pragma unroll
            for (int i = 0; i < 4; i++)
                #pragma unroll
                for (int j = 0; j < 4; j++)
                    acc[i][j] += a[i] * w[j];
        }
        __syncthreads();
    }
    #pragma unroll
    for (int i = 0; i < 4; i++) {
        const int m = bm + ty * 4 + i;
        #pragma unroll
        for (int j = 0; j < 4; j++) {
            const int nn = bn + tx * 4 + j;
            if (nn < CC) out[(size_t)m * CC + nn] = acc[i][j] + bg[nn];
        }
    }
}

// ---------------------------------------------------------------------------
extern "C" void kernel_launch(void* const* d_in, const int* in_sizes, int n_in,
                              void* d_out, int out_size)
{
    const float* batch_H = (const float*)d_in[0];
    const int*   text    = (const int*)  d_in[1];
    const float* W_i2h   = (const float*)d_in[2];
    const float* W_h2h   = (const float*)d_in[3];
    const float* b_h2h   = (const float*)d_in[4];
    const float* W_score = (const float*)d_in[5];
    const float* W_ih    = (const float*)d_in[6];
    const float* W_hh    = (const float*)d_in[7];
    const float* b_ih    = (const float*)d_in[8];
    const float* b_hh    = (const float*)d_in[9];
    const float* W_gen   = (const float*)d_in[10];
    const float* b_gen   = (const float*)d_in[11];
    float* out = (float*)d_out;

    // H_proj precompute: (2048*64 / 64, 256/64)
    hproj_kernel<<<dim3((BB * TT) / 64, HH / 64), 256>>>(batch_H, W_i2h);

    // Recurrence: 128 CTAs x 256 threads, ~70.7 KB dynamic smem
    const int smem_bytes = (4 * MROWS * HH + MROWS * TT + HH) * 4 + MROWS * 4;
    cudaFuncSetAttribute(recur_kernel, cudaFuncAttributeMaxDynamicSharedMemorySize,
                         smem_bytes);
    recur_kernel<<<BB / MROWS, 256, smem_bytes>>>(
        batch_H, text, W_h2h, b_h2h, W_score, W_ih, W_hh, b_ih, b_hh);

    // Final projection: (53248/64, ceil(1000/64))
    gen_kernel<<<dim3((BB * SS) / 64, (CC + 63) / 64), 256>>>(W_gen, b_gen, out);
}

// round 4
// speedup vs baseline: 1.1370x; 1.1370x over previous
#include <cuda_runtime.h>
#include <cstdint>

#define BB   2048
#define TT   64
#define DD   256
#define HH   256
#define CC   1000
#define SS   26
#define DCC  1256   // D + C
#define MROWS 16    // batch rows per recurrence CTA

// Scratch (allocation-free: __device__ globals)
__device__ float g_Hproj[(size_t)BB * TT * HH];    // 128 MB
__device__ float g_hidden[(size_t)BB * SS * HH];   // 52 MB
__device__ float4 g_Wgates[512 * 256];             // [k=0..511][u=0..255] 4 gates packed
__device__ float  g_Wh2hT[256 * 256];              // [k][n]

__device__ __forceinline__ float ftanh(float x) {
    float y;
    asm("tanh.approx.f32 %0, %1;" : "=f"(y) : "f"(x));
    return y;
}
__device__ __forceinline__ float fsig(float x) {
    return 0.5f * ftanh(0.5f * x) + 0.5f;
}

// ---------------------------------------------------------------------------
// Pack kernel: transpose weights into k-major, gate-interleaved layout.
// grid = 512 blocks (k), 256 threads (u).
// ---------------------------------------------------------------------------
__global__ void __launch_bounds__(256) pack_kernel(
    const float* __restrict__ W_ih, const float* __restrict__ W_hh,
    const float* __restrict__ W_h2h)
{
    const int k = blockIdx.x;
    const int u = threadIdx.x;
    float4 v;
    if (k < 256) {
        v.x = W_ih[(size_t)(u      ) * DCC + k];
        v.y = W_ih[(size_t)(u + 256) * DCC + k];
        v.z = W_ih[(size_t)(u + 512) * DCC + k];
        v.w = W_ih[(size_t)(u + 768) * DCC + k];
        g_Wh2hT[k * 256 + u] = W_h2h[u * 256 + k];
    } else {
        const int kk = k - 256;
        v.x = W_hh[(size_t)(u      ) * HH + kk];
        v.y = W_hh[(size_t)(u + 256) * HH + kk];
        v.z = W_hh[(size_t)(u + 512) * HH + kk];
        v.w = W_hh[(size_t)(u + 768) * HH + kk];
    }
    g_Wgates[k * 256 + u] = v;
}

// ---------------------------------------------------------------------------
// Generic NT GEMM tile: C[M,N] = A[M,K] * B[N,K]^T, BM=BN=128, BK=8,
// 256 threads, 8x8 micro. Used for hproj and gen.
// ---------------------------------------------------------------------------
__global__ void __launch_bounds__(256) hproj_kernel(
    const float* __restrict__ A, const float* __restrict__ W)
{
    __shared__ float As[8][132];
    __shared__ float Ws[8][132];
    const int bm = blockIdx.x * 128;
    const int bn = blockIdx.y * 128;
    const int tid = threadIdx.x;
    const int tx = tid & 15, ty = tid >> 4;
    const int lr = tid >> 1;            // 0..127
    const int lk = (tid & 1) * 4;       // 0 or 4

    float acc[8][8] = {};
    for (int k0 = 0; k0 < DD; k0 += 8) {
        float4 av = *(const float4*)(A + (size_t)(bm + lr) * DD + k0 + lk);
        float4 wv = *(const float4*)(W + (size_t)(bn + lr) * DD + k0 + lk);
        As[lk + 0][lr] = av.x; As[lk + 1][lr] = av.y;
        As[lk + 2][lr] = av.z; As[lk + 3][lr] = av.w;
        Ws[lk + 0][lr] = wv.x; Ws[lk + 1][lr] = wv.y;
        Ws[lk + 2][lr] = wv.z; Ws[lk + 3][lr] = wv.w;
        __syncthreads();
        #pragma unroll
        for (int kk = 0; kk < 8; kk++) {
            float4 a0 = *(const float4*)&As[kk][ty * 8];
            float4 a1 = *(const float4*)&As[kk][ty * 8 + 4];
            float4 b0 = *(const float4*)&Ws[kk][tx * 8];
            float4 b1 = *(const float4*)&Ws[kk][tx * 8 + 4];
            float a[8] = {a0.x,a0.y,a0.z,a0.w,a1.x,a1.y,a1.z,a1.w};
            float b[8] = {b0.x,b0.y,b0.z,b0.w,b1.x,b1.y,b1.z,b1.w};
            #pragma unroll
            for (int i = 0; i < 8; i++)
                #pragma unroll
                for (int j = 0; j < 8; j++)
                    acc[i][j] += a[i] * b[j];
        }
        __syncthreads();
    }
    #pragma unroll
    for (int i = 0; i < 8; i++) {
        float* dst = g_Hproj + (size_t)(bm + ty * 8 + i) * HH + bn + tx * 8;
        *(float4*)dst       = make_float4(acc[i][0], acc[i][1], acc[i][2], acc[i][3]);
        *(float4*)(dst + 4) = make_float4(acc[i][4], acc[i][5], acc[i][6], acc[i][7]);
    }
}

__global__ void __launch_bounds__(256) gen_kernel(
    const float* __restrict__ Wg, const float* __restrict__ bg,
    float* __restrict__ out)
{
    __shared__ float As[8][132];
    __shared__ float Ws[8][132];
    const int bm = blockIdx.x * 128;
    const int bn = blockIdx.y * 128;
    const int tid = threadIdx.x;
    const int tx = tid & 15, ty = tid >> 4;
    const int lr = tid >> 1;
    const int lk = (tid & 1) * 4;

    float acc[8][8] = {};
    for (int k0 = 0; k0 < HH; k0 += 8) {
        float4 av = *(const float4*)(g_hidden + (size_t)(bm + lr) * HH + k0 + lk);
        float4 wv = make_float4(0.f, 0.f, 0.f, 0.f);
        if (bn + lr < CC)
            wv = *(const float4*)(Wg + (size_t)(bn + lr) * HH + k0 + lk);
        As[lk + 0][lr] = av.x; As[lk + 1][lr] = av.y;
        As[lk + 2][lr] = av.z; As[lk + 3][lr] = av.w;
        Ws[lk + 0][lr] = wv.x; Ws[lk + 1][lr] = wv.y;
        Ws[lk + 2][lr] = wv.z; Ws[lk + 3][lr] = wv.w;
        __syncthreads();
        #pragma unroll
        for (int kk = 0; kk < 8; kk++) {
            float4 a0 = *(const float4*)&As[kk][ty * 8];
            float4 a1 = *(const float4*)&As[kk][ty * 8 + 4];
            float4 b0 = *(const float4*)&Ws[kk][tx * 8];
            float4 b1 = *(const float4*)&Ws[kk][tx * 8 + 4];
            float a[8] = {a0.x,a0.y,a0.z,a0.w,a1.x,a1.y,a1.z,a1.w};
            float b[8] = {b0.x,b0.y,b0.z,b0.w,b1.x,b1.y,b1.z,b1.w};
            #pragma unroll
            for (int i = 0; i < 8; i++)
                #pragma unroll
                for (int j = 0; j < 8; j++)
                    acc[i][j] += a[i] * b[j];
        }
        __syncthreads();
    }
    #pragma unroll
    for (int i = 0; i < 8; i++) {
        const int m = bm + ty * 8 + i;
        #pragma unroll
        for (int j = 0; j < 8; j++) {
            const int nn = bn + tx * 8 + j;
            if (nn < CC) out[(size_t)m * CC + nn] = acc[i][j] + bg[nn];
        }
    }
}

// ---------------------------------------------------------------------------
// Persistent recurrence. grid=128 CTAs, 256 threads, M=16 rows/CTA.
// ---------------------------------------------------------------------------
__global__ void __launch_bounds__(256) recur_kernel(
    const float* __restrict__ batch_H, const int* __restrict__ text,
    const float* __restrict__ b_h2h,   const float* __restrict__ W_score,
    const float* __restrict__ W_ih,
    const float* __restrict__ b_ih,    const float* __restrict__ b_hh)
{
    extern __shared__ float sm[];
    float* sh_h   = sm;                      // 16*256 (m-major)
    float* sh_hp  = sh_h   + MROWS * HH;     // 16*256 (m-major)
    float* sh_ctx = sh_hp  + MROWS * HH;     // 16*256 (m-major)
    float* sh_e   = sh_ctx + MROWS * HH;     // 16*64
    float* sh_ws  = sh_e   + MROWS * TT;     // 256
    int*   sh_ch  = (int*)(sh_ws + HH);      // 16

    const int tid  = threadIdx.x;
    const int warp = tid >> 5, lane = tid & 31;
    const int r0   = blockIdx.x * MROWS;

    for (int i = tid; i < MROWS * HH; i += 256) sh_h[i] = 0.f;
    sh_ws[tid] = W_score[tid];

    // Per-thread persistent LSTM cell state (thread u owns unit u, all 16 rows)
    float cst[MROWS];
    #pragma unroll
    for (int m = 0; m < MROWS; m++) cst[m] = 0.f;

    const float bb_h2h = b_h2h[tid];
    const float bi0 = b_ih[tid      ] + b_hh[tid      ];
    const float bi1 = b_ih[tid + 256] + b_hh[tid + 256];
    const float bi2 = b_ih[tid + 512] + b_hh[tid + 512];
    const float bi3 = b_ih[tid + 768] + b_hh[tid + 768];
    __syncthreads();

    for (int s = 0; s < SS; s++) {
        if (tid < MROWS) sh_ch[tid] = text[(r0 + tid) * SS + s];

        // ---- Stage 1: hp = h @ W_h2h^T + b. thread n, coalesced Wt loads --
        {
            const int n = tid;
            float acc[MROWS];
            #pragma unroll
            for (int m = 0; m < MROWS; m++) acc[m] = bb_h2h;
            #pragma unroll 4
            for (int k = 0; k < HH; k++) {
                const float w = g_Wh2hT[k * 256 + n];
                #pragma unroll
                for (int m = 0; m < MROWS; m++)
                    acc[m] += w * sh_h[m * HH + k];
            }
            #pragma unroll
            for (int m = 0; m < MROWS; m++) sh_hp[m * HH + n] = acc[m];
        }
        __syncthreads();

        // ---- Stage 2: e[m,t] = Wscore . tanh(Hproj[m,t,:] + hp[m,:]) ------
        // Each warp processes 4 rows concurrently for memory-level parallelism
        for (int pb = warp * 4; pb < MROWS * TT; pb += 32) {
            float sum[4];
            #pragma unroll
            for (int q = 0; q < 4; q++) sum[q] = 0.f;
            #pragma unroll
            for (int i = 0; i < 2; i++) {
                const int h0 = i * 128 + lane * 4;
                const float4 w = *(const float4*)(sh_ws + h0);
                #pragma unroll
                for (int q = 0; q < 4; q++) {
                    const int p = pb + q;
                    const int m = p >> 6, t = p & 63;
                    const float4 a = *(const float4*)(g_Hproj +
                        ((size_t)(r0 + m) * TT + t) * HH + h0);
                    const float4 b = *(const float4*)(sh_hp + m * HH + h0);
                    sum[q] += w.x * ftanh(a.x + b.x) + w.y * ftanh(a.y + b.y)
                            + w.z * ftanh(a.z + b.z) + w.w * ftanh(a.w + b.w);
                }
            }
            #pragma unroll
            for (int q = 0; q < 4; q++) {
                float sq = sum[q];
                #pragma unroll
                for (int o = 16; o > 0; o >>= 1)
                    sq += __shfl_xor_sync(0xffffffffu, sq, o);
                if (lane == 0) sh_e[pb + q] = sq;
            }
        }
        __syncthreads();

        // ---- Stage 3: softmax over t (warp handles 2 rows) ----------------
        #pragma unroll
        for (int mm = 0; mm < 2; mm++) {
            const int m = warp * 2 + mm;
            float e0 = sh_e[m * TT + lane];
            float e1 = sh_e[m * TT + 32 + lane];
            float mx = fmaxf(e0, e1);
            #pragma unroll
            for (int o = 16; o > 0; o >>= 1)
                mx = fmaxf(mx, __shfl_xor_sync(0xffffffffu, mx, o));
            float x0 = __expf(e0 - mx), x1 = __expf(e1 - mx);
            float sume = x0 + x1;
            #pragma unroll
            for (int o = 16; o > 0; o >>= 1)
                sume += __shfl_xor_sync(0xffffffffu, sume, o);
            float inv = __frcp_rn(sume);
            sh_e[m * TT + lane]      = x0 * inv;
            sh_e[m * TT + 32 + lane] = x1 * inv;
        }
        __syncthreads();

        // ---- Stage 4: context[m,d] = sum_t alpha[m,t] * batch_H[m,t,d] ----
        // thread = (dg = tid&63 -> d4, mgrp = tid>>6 -> 4 rows). float4 loads.
        {
            const int dg = tid & 63;
            const int mgrp = tid >> 6;
            #pragma unroll
            for (int mi = 0; mi < 4; mi++) {
                const int m = mgrp * 4 + mi;
                const float* bh = batch_H + ((size_t)(r0 + m) * TT) * DD + dg * 4;
                float4 acc = make_float4(0.f, 0.f, 0.f, 0.f);
                #pragma unroll 8
                for (int t = 0; t < TT; t++) {
                    const float a  = sh_e[m * TT + t];
                    const float4 v = *(const float4*)(bh + (size_t)t * DD);
                    acc.x += a * v.x; acc.y += a * v.y;
                    acc.z += a * v.z; acc.w += a * v.w;
                }
                *(float4*)(sh_ctx + m * HH + dg * 4) = acc;
            }
        }
        __syncthreads();

        // ---- Stage 5: gates + LSTM. thread u owns unit u (4 packed gates) -
        {
            const int u = tid;
            float a0[MROWS], a1[MROWS], a2[MROWS], a3[MROWS];
            #pragma unroll
            for (int m = 0; m < MROWS; m++) {
                const int ch = 256 + sh_ch[m];   // one-hot => column gather
                a0[m] = bi0 + W_ih[(size_t)(u      ) * DCC + ch];
                a1[m] = bi1 + W_ih[(size_t)(u + 256) * DCC + ch];
                a2[m] = bi2 + W_ih[(size_t)(u + 512) * DCC + ch];
                a3[m] = bi3 + W_ih[(size_t)(u + 768) * DCC + ch];
            }
            // context part: coalesced packed weights
            #pragma unroll 2
            for (int k = 0; k < 256; k++) {
                const float4 w = g_Wgates[k * 256 + u];
                #pragma unroll
                for (int m = 0; m < MROWS; m++) {
                    const float x = sh_ctx[m * HH + k];
                    a0[m] += w.x * x; a1[m] += w.y * x;
                    a2[m] += w.z * x; a3[m] += w.w * x;
                }
            }
            // hidden part
            #pragma unroll 2
            for (int k = 0; k < 256; k++) {
                const float4 w = g_Wgates[(k + 256) * 256 + u];
                #pragma unroll
                for (int m = 0; m < MROWS; m++) {
                    const float x = sh_h[m * HH + k];
                    a0[m] += w.x * x; a1[m] += w.y * x;
                    a2[m] += w.z * x; a3[m] += w.w * x;
                }
            }
            // LSTM pointwise (gate order i,f,g,o), c in registers
            float hn[MROWS];
            #pragma unroll
            for (int m = 0; m < MROWS; m++) {
                const float cnew = fsig(a1[m]) * cst[m] + fsig(a0[m]) * ftanh(a2[m]);
                cst[m] = cnew;
                hn[m] = fsig(a3[m]) * ftanh(cnew);
                g_hidden[((size_t)(r0 + m) * SS + s) * HH + u] = hn[m];
            }
            __syncthreads();   // all reads of sh_h done before overwrite
            #pragma unroll
            for (int m = 0; m < MROWS; m++) sh_h[m * HH + u] = hn[m];
        }
        __syncthreads();
    }
}

// ---------------------------------------------------------------------------
extern "C" void kernel_launch(void* const* d_in, const int* in_sizes, int n_in,
                              void* d_out, int out_size)
{
    const float* batch_H = (const float*)d_in[0];
    const int*   text    = (const int*)  d_in[1];
    const float* W_i2h   = (const float*)d_in[2];
    const float* W_h2h   = (const float*)d_in[3];
    const float* b_h2h   = (const float*)d_in[4];
    const float* W_score = (const float*)d_in[5];
    const float* W_ih    = (const float*)d_in[6];
    const float* W_hh    = (const float*)d_in[7];
    const float* b_ih    = (const float*)d_in[8];
    const float* b_hh    = (const float*)d_in[9];
    const float* W_gen   = (const float*)d_in[10];
    const float* b_gen   = (const float*)d_in[11];
    float* out = (float*)d_out;

    // Weight pack/transpose (runs every launch; ~trivial)
    pack_kernel<<<512, 256>>>(W_ih, W_hh, W_h2h);

    // H_proj precompute: M=131072, N=256 -> grid (1024, 2)
    hproj_kernel<<<dim3((BB * TT) / 128, HH / 128), 256>>>(batch_H, W_i2h);

    // Recurrence: 128 CTAs x 256 threads
    const int smem_bytes = (3 * MROWS * HH + MROWS * TT + HH) * 4 + MROWS * 4;
    cudaFuncSetAttribute(recur_kernel, cudaFuncAttributeMaxDynamicSharedMemorySize,
                         smem_bytes);
    recur_kernel<<<BB / MROWS, 256, smem_bytes>>>(
        batch_H, text, b_h2h, W_score, W_ih, b_ih, b_hh);

    // Final projection: M=53248, N=1000 -> grid (416, 8)
    gen_kernel<<<dim3((BB * SS) / 128, (CC + 127) / 128), 256>>>(W_gen, b_gen, out);
}

// round 6
// speedup vs baseline: 1.5181x; 1.3352x over previous
#include <cuda_runtime.h>
#include <cstdint>

#define BB   2048
#define TT   64
#define DD   256
#define HH   256
#define CC   1000
#define SS   26
#define DCC  1256   // D + C
#define MROWS 16    // batch rows per recurrence CTA
#define MH   8      // rows per thread-half in recurrence

// Scratch (allocation-free: __device__ globals)
__device__ float g_Hproj[(size_t)BB * TT * HH];    // 128 MB
__device__ float g_hidden[(size_t)BB * SS * HH];   // 52 MB
__device__ float4 g_Wgates[512 * 256];             // [k][u] 4 gates packed
__device__ float  g_Wh2hT[256 * 256];              // [k][n]

__device__ __forceinline__ float ftanh(float x) {
    float y;
    asm("tanh.approx.f32 %0, %1;" : "=f"(y) : "f"(x));
    return y;
}
__device__ __forceinline__ float fsig(float x) {
    return 0.5f * ftanh(0.5f * x) + 0.5f;
}

// ---------------------------------------------------------------------------
// Pack kernel: transpose weights into k-major, gate-interleaved layout.
// ---------------------------------------------------------------------------
__global__ void __launch_bounds__(256) pack_kernel(
    const float* __restrict__ W_ih, const float* __restrict__ W_hh,
    const float* __restrict__ W_h2h)
{
    const int k = blockIdx.x;
    const int u = threadIdx.x;
    float4 v;
    if (k < 256) {
        v.x = W_ih[(size_t)(u      ) * DCC + k];
        v.y = W_ih[(size_t)(u + 256) * DCC + k];
        v.z = W_ih[(size_t)(u + 512) * DCC + k];
        v.w = W_ih[(size_t)(u + 768) * DCC + k];
        g_Wh2hT[k * 256 + u] = W_h2h[u * 256 + k];
    } else {
        const int kk = k - 256;
        v.x = W_hh[(size_t)(u      ) * HH + kk];
        v.y = W_hh[(size_t)(u + 256) * HH + kk];
        v.z = W_hh[(size_t)(u + 512) * HH + kk];
        v.w = W_hh[(size_t)(u + 768) * HH + kk];
    }
    g_Wgates[k * 256 + u] = v;
}

// ---------------------------------------------------------------------------
// NT GEMM 128x128x8, 256 threads, 8x8 micro, double-buffered smem with
// register-staged prefetch (1 sync per K-tile).
// ---------------------------------------------------------------------------
__global__ void __launch_bounds__(256) hproj_kernel(
    const float* __restrict__ A, const float* __restrict__ W)
{
    __shared__ float As[2][8][132];
    __shared__ float Ws[2][8][132];
    const int bm = blockIdx.x * 128;
    const int bn = blockIdx.y * 128;
    const int tid = threadIdx.x;
    const int tx = tid & 15, ty = tid >> 4;
    const int lr = tid >> 1;            // 0..127
    const int lk = (tid & 1) * 4;       // 0 or 4

    const float* arow = A + (size_t)(bm + lr) * DD + lk;
    const float* wrow = W + (size_t)(bn + lr) * DD + lk;

    // prologue: tile 0
    {
        float4 av = *(const float4*)arow;
        float4 wv = *(const float4*)wrow;
        As[0][lk+0][lr]=av.x; As[0][lk+1][lr]=av.y; As[0][lk+2][lr]=av.z; As[0][lk+3][lr]=av.w;
        Ws[0][lk+0][lr]=wv.x; Ws[0][lk+1][lr]=wv.y; Ws[0][lk+2][lr]=wv.z; Ws[0][lk+3][lr]=wv.w;
    }
    __syncthreads();

    float acc[8][8] = {};
    int p = 0;
    const int KT = DD / 8;
    for (int kt = 0; kt < KT; kt++) {
        float4 nav, nwv;
        const bool more = (kt + 1 < KT);
        if (more) {
            nav = *(const float4*)(arow + (kt + 1) * 8);
            nwv = *(const float4*)(wrow + (kt + 1) * 8);
        }
        #pragma unroll
        for (int kk = 0; kk < 8; kk++) {
            float4 a0 = *(const float4*)&As[p][kk][ty * 8];
            float4 a1 = *(const float4*)&As[p][kk][ty * 8 + 4];
            float4 b0 = *(const float4*)&Ws[p][kk][tx * 8];
            float4 b1 = *(const float4*)&Ws[p][kk][tx * 8 + 4];
            float a[8] = {a0.x,a0.y,a0.z,a0.w,a1.x,a1.y,a1.z,a1.w};
            float b[8] = {b0.x,b0.y,b0.z,b0.w,b1.x,b1.y,b1.z,b1.w};
            #pragma unroll
            for (int i = 0; i < 8; i++)
                #pragma unroll
                for (int j = 0; j < 8; j++)
                    acc[i][j] += a[i] * b[j];
        }
        if (more) {
            const int q = p ^ 1;
            As[q][lk+0][lr]=nav.x; As[q][lk+1][lr]=nav.y; As[q][lk+2][lr]=nav.z; As[q][lk+3][lr]=nav.w;
            Ws[q][lk+0][lr]=nwv.x; Ws[q][lk+1][lr]=nwv.y; Ws[q][lk+2][lr]=nwv.z; Ws[q][lk+3][lr]=nwv.w;
        }
        __syncthreads();
        p ^= 1;
    }
    #pragma unroll
    for (int i = 0; i < 8; i++) {
        float* dst = g_Hproj + (size_t)(bm + ty * 8 + i) * HH + bn + tx * 8;
        *(float4*)dst       = make_float4(acc[i][0], acc[i][1], acc[i][2], acc[i][3]);
        *(float4*)(dst + 4) = make_float4(acc[i][4], acc[i][5], acc[i][6], acc[i][7]);
    }
}

__global__ void __launch_bounds__(256) gen_kernel(
    const float* __restrict__ Wg, const float* __restrict__ bg,
    float* __restrict__ out)
{
    __shared__ float As[2][8][132];
    __shared__ float Ws[2][8][132];
    const int bm = blockIdx.x * 128;
    const int bn = blockIdx.y * 128;
    const int tid = threadIdx.x;
    const int tx = tid & 15, ty = tid >> 4;
    const int lr = tid >> 1;
    const int lk = (tid & 1) * 4;

    const float* arow = g_hidden + (size_t)(bm + lr) * HH + lk;
    const bool wok = (bn + lr < CC);
    const float* wrow = Wg + (size_t)(bn + lr) * HH + lk;

    {
        float4 av = *(const float4*)arow;
        float4 wv = wok ? *(const float4*)wrow : make_float4(0.f,0.f,0.f,0.f);
        As[0][lk+0][lr]=av.x; As[0][lk+1][lr]=av.y; As[0][lk+2][lr]=av.z; As[0][lk+3][lr]=av.w;
        Ws[0][lk+0][lr]=wv.x; Ws[0][lk+1][lr]=wv.y; Ws[0][lk+2][lr]=wv.z; Ws[0][lk+3][lr]=wv.w;
    }
    __syncthreads();

    float acc[8][8] = {};
    int p = 0;
    const int KT = HH / 8;
    for (int kt = 0; kt < KT; kt++) {
        float4 nav, nwv;
        const bool more = (kt + 1 < KT);
        if (more) {
            nav = *(const float4*)(arow + (kt + 1) * 8);
            nwv = wok ? *(const float4*)(wrow + (kt + 1) * 8) : make_float4(0.f,0.f,0.f,0.f);
        }
        #pragma unroll
        for (int kk = 0; kk < 8; kk++) {
            float4 a0 = *(const float4*)&As[p][kk][ty * 8];
            float4 a1 = *(const float4*)&As[p][kk][ty * 8 + 4];
            float4 b0 = *(const float4*)&Ws[p][kk][tx * 8];
            float4 b1 = *(const float4*)&Ws[p][kk][tx * 8 + 4];
            float a[8] = {a0.x,a0.y,a0.z,a0.w,a1.x,a1.y,a1.z,a1.w};
            float b[8] = {b0.x,b0.y,b0.z,b0.w,b1.x,b1.y,b1.z,b1.w};
            #pragma unroll
            for (int i = 0; i < 8; i++)
                #pragma unroll
                for (int j = 0; j < 8; j++)
                    acc[i][j] += a[i] * b[j];
        }
        if (more) {
            const int q = p ^ 1;
            As[q][lk+0][lr]=nav.x; As[q][lk+1][lr]=nav.y; As[q][lk+2][lr]=nav.z; As[q][lk+3][lr]=nav.w;
            Ws[q][lk+0][lr]=nwv.x; Ws[q][lk+1][lr]=nwv.y; Ws[q][lk+2][lr]=nwv.z; Ws[q][lk+3][lr]=nwv.w;
        }
        __syncthreads();
        p ^= 1;
    }
    #pragma unroll
    for (int i = 0; i < 8; i++) {
        const int m = bm + ty * 8 + i;
        #pragma unroll
        for (int j = 0; j < 8; j++) {
            const int nn = bn + tx * 8 + j;
            if (nn < CC) out[(size_t)m * CC + nn] = acc[i][j] + bg[nn];
        }
    }
}

// ---------------------------------------------------------------------------
// Persistent recurrence. grid=128 CTAs, 512 threads.
// Thread (u = tid&255, mh = tid>>8): unit u, rows [mh*8, mh*8+8).
// ---------------------------------------------------------------------------
__global__ void __launch_bounds__(512) recur_kernel(
    const float* __restrict__ batch_H, const int* __restrict__ text,
    const float* __restrict__ b_h2h,   const float* __restrict__ W_score,
    const float* __restrict__ W_ih,
    const float* __restrict__ b_ih,    const float* __restrict__ b_hh)
{
    extern __shared__ float sm[];
    float* sh_h   = sm;                      // 16*256 (m-major)
    float* sh_hp  = sh_h   + MROWS * HH;     // 16*256
    float* sh_ctx = sh_hp  + MROWS * HH;     // 16*256
    float* sh_e   = sh_ctx + MROWS * HH;     // 16*64
    float* sh_ws  = sh_e   + MROWS * TT;     // 256
    int*   sh_ch  = (int*)(sh_ws + HH);      // 16

    const int tid  = threadIdx.x;
    const int warp = tid >> 5, lane = tid & 31;
    const int u    = tid & 255;
    const int mh   = tid >> 8;      // 0 or 1
    const int m0   = mh * MH;
    const int r0   = blockIdx.x * MROWS;

    for (int i = tid; i < MROWS * HH; i += 512) sh_h[i] = 0.f;
    if (tid < 256) sh_ws[tid] = W_score[tid];

    float cst[MH];
    #pragma unroll
    for (int m = 0; m < MH; m++) cst[m] = 0.f;

    const float bb_h2h = b_h2h[u];
    const float bi0 = b_ih[u      ] + b_hh[u      ];
    const float bi1 = b_ih[u + 256] + b_hh[u + 256];
    const float bi2 = b_ih[u + 512] + b_hh[u + 512];
    const float bi3 = b_ih[u + 768] + b_hh[u + 768];
    __syncthreads();

    for (int s = 0; s < SS; s++) {
        if (tid < MROWS) sh_ch[tid] = text[(r0 + tid) * SS + s];

        // ---- Stage 1: hp = h @ W_h2h^T + b --------------------------------
        {
            float acc[MH];
            #pragma unroll
            for (int m = 0; m < MH; m++) acc[m] = bb_h2h;
            #pragma unroll 4
            for (int k = 0; k < HH; k++) {
                const float w = g_Wh2hT[k * 256 + u];
                #pragma unroll
                for (int m = 0; m < MH; m++)
                    acc[m] += w * sh_h[(m0 + m) * HH + k];
            }
            #pragma unroll
            for (int m = 0; m < MH; m++) sh_hp[(m0 + m) * HH + u] = acc[m];
        }
        __syncthreads();

        // ---- Stage 2: e[m,t] = Wscore . tanh(Hproj + hp) ------------------
        for (int pb = warp * 4; pb < MROWS * TT; pb += 64) {
            float sum[4];
            #pragma unroll
            for (int q = 0; q < 4; q++) sum[q] = 0.f;
            #pragma unroll
            for (int i = 0; i < 2; i++) {
                const int h0 = i * 128 + lane * 4;
                const float4 w = *(const float4*)(sh_ws + h0);
                #pragma unroll
                for (int q = 0; q < 4; q++) {
                    const int pp = pb + q;
                    const int m = pp >> 6, t = pp & 63;
                    const float4 a = *(const float4*)(g_Hproj +
                        ((size_t)(r0 + m) * TT + t) * HH + h0);
                    const float4 b = *(const float4*)(sh_hp + m * HH + h0);
                    sum[q] += w.x * ftanh(a.x + b.x) + w.y * ftanh(a.y + b.y)
                            + w.z * ftanh(a.z + b.z) + w.w * ftanh(a.w + b.w);
                }
            }
            #pragma unroll
            for (int q = 0; q < 4; q++) {
                float sq = sum[q];
                #pragma unroll
                for (int o = 16; o > 0; o >>= 1)
                    sq += __shfl_xor_sync(0xffffffffu, sq, o);
                if (lane == 0) sh_e[pb + q] = sq;
            }
        }
        __syncthreads();

        // ---- Stage 3: softmax over t, 1 row per warp ----------------------
        {
            const int m = warp;
            float e0 = sh_e[m * TT + lane];
            float e1 = sh_e[m * TT + 32 + lane];
            float mx = fmaxf(e0, e1);
            #pragma unroll
            for (int o = 16; o > 0; o >>= 1)
                mx = fmaxf(mx, __shfl_xor_sync(0xffffffffu, mx, o));
            float x0 = __expf(e0 - mx), x1 = __expf(e1 - mx);
            float sume = x0 + x1;
            #pragma unroll
            for (int o = 16; o > 0; o >>= 1)
                sume += __shfl_xor_sync(0xffffffffu, sume, o);
            float inv = __frcp_rn(sume);
            sh_e[m * TT + lane]      = x0 * inv;
            sh_e[m * TT + 32 + lane] = x1 * inv;
        }
        __syncthreads();

        // ---- Stage 4: context[m,d] = sum_t alpha[m,t] * batch_H[m,t,d] ----
        {
            const int dg = tid & 63;        // d4 group
            const int mg = tid >> 6;        // 0..7 -> 2 rows each
            #pragma unroll
            for (int mi = 0; mi < 2; mi++) {
                const int m = mg * 2 + mi;
                const float* bh = batch_H + ((size_t)(r0 + m) * TT) * DD + dg * 4;
                float4 acc = make_float4(0.f, 0.f, 0.f, 0.f);
                #pragma unroll 8
                for (int t = 0; t < TT; t++) {
                    const float a  = sh_e[m * TT + t];
                    const float4 v = *(const float4*)(bh + (size_t)t * DD);
                    acc.x += a * v.x; acc.y += a * v.y;
                    acc.z += a * v.z; acc.w += a * v.w;
                }
                *(float4*)(sh_ctx + m * HH + dg * 4) = acc;
            }
        }
        __syncthreads();

        // ---- Stage 5: gates + LSTM (unit u, rows m0..m0+7) ----------------
        {
            float a0[MH], a1[MH], a2[MH], a3[MH];
            #pragma unroll
            for (int m = 0; m < MH; m++) {
                const int ch = 256 + sh_ch[m0 + m];   // one-hot column gather
                a0[m] = bi0 + W_ih[(size_t)(u      ) * DCC + ch];
                a1[m] = bi1 + W_ih[(size_t)(u + 256) * DCC + ch];
                a2[m] = bi2 + W_ih[(size_t)(u + 512) * DCC + ch];
                a3[m] = bi3 + W_ih[(size_t)(u + 768) * DCC + ch];
            }
            #pragma unroll 4
            for (int k = 0; k < 256; k++) {
                const float4 w = g_Wgates[k * 256 + u];
                #pragma unroll
                for (int m = 0; m < MH; m++) {
                    const float x = sh_ctx[(m0 + m) * HH + k];
                    a0[m] += w.x * x; a1[m] += w.y * x;
                    a2[m] += w.z * x; a3[m] += w.w * x;
                }
            }
            #pragma unroll 4
            for (int k = 0; k < 256; k++) {
                const float4 w = g_Wgates[(k + 256) * 256 + u];
                #pragma unroll
                for (int m = 0; m < MH; m++) {
                    const float x = sh_h[(m0 + m) * HH + k];
                    a0[m] += w.x * x; a1[m] += w.y * x;
                    a2[m] += w.z * x; a3[m] += w.w * x;
                }
            }
            float hn[MH];
            #pragma unroll
            for (int m = 0; m < MH; m++) {
                const float cnew = fsig(a1[m]) * cst[m] + fsig(a0[m]) * ftanh(a2[m]);
                cst[m] = cnew;
                hn[m] = fsig(a3[m]) * ftanh(cnew);
                g_hidden[((size_t)(r0 + m0 + m) * SS + s) * HH + u] = hn[m];
            }
            __syncthreads();   // all reads of sh_h done before overwrite
            #pragma unroll
            for (int m = 0; m < MH; m++) sh_h[(m0 + m) * HH + u] = hn[m];
        }
        __syncthreads();
    }
}

// ---------------------------------------------------------------------------
extern "C" void kernel_launch(void* const* d_in, const int* in_sizes, int n_in,
                              void* d_out, int out_size)
{
    const float* batch_H = (const float*)d_in[0];
    const int*   text    = (const int*)  d_in[1];
    const float* W_i2h   = (const float*)d_in[2];
    const float* W_h2h   = (const float*)d_in[3];
    const float* b_h2h   = (const float*)d_in[4];
    const float* W_score = (const float*)d_in[5];
    const float* W_ih    = (const float*)d_in[6];
    const float* W_hh    = (const float*)d_in[7];
    const float* b_ih    = (const float*)d_in[8];
    const float* b_hh    = (const float*)d_in[9];
    const float* W_gen   = (const float*)d_in[10];
    const float* b_gen   = (const float*)d_in[11];
    float* out = (float*)d_out;

    pack_kernel<<<512, 256>>>(W_ih, W_hh, W_h2h);

    hproj_kernel<<<dim3((BB * TT) / 128, HH / 128), 256>>>(batch_H, W_i2h);

    const int smem_bytes = (3 * MROWS * HH + MROWS * TT + HH) * 4 + MROWS * 4;
    cudaFuncSetAttribute(recur_kernel, cudaFuncAttributeMaxDynamicSharedMemorySize,
                         smem_bytes);
    recur_kernel<<<BB / MROWS, 512, smem_bytes>>>(
        batch_H, text, b_h2h, W_score, W_ih, b_ih, b_hh);

    gen_kernel<<<dim3((BB * SS) / 128, (CC + 127) / 128), 256>>>(W_gen, b_gen, out);
}

// round 7
// speedup vs baseline: 2.0801x; 1.3702x over previous
#include <cuda_runtime.h>
#include <cstdint>

#define BB   2048
#define TT   64
#define DD   256
#define HH   256
#define CC   1000
#define SS   26
#define DCC  1256   // D + C
#define MROWS 16    // batch rows per recurrence CTA
#define XS   516    // sh_x row stride (floats): %4==0, %32==4 -> conflict-free frags

// Scratch (allocation-free: __device__ globals)
__device__ float  g_Hproj[(size_t)BB * TT * HH];   // 128 MB
__device__ float  g_hidden[(size_t)BB * SS * HH];  // 52 MB
__device__ float2 g_WfragGates[128 * 64 * 32];     // 2 MB   B-frags, gates GEMM
__device__ float2 g_WfragH2h[32 * 32 * 32];        // 256 KB B-frags, h2h GEMM
__device__ float  g_WohP[1000 * 1024];             // 4 MB   one-hot cols, packed order
__device__ float  g_biasP[1024];                   // b_ih+b_hh, packed order

__device__ __forceinline__ float ftanh(float x) {
    float y;
    asm("tanh.approx.f32 %0, %1;" : "=f"(y) : "f"(x));
    return y;
}
__device__ __forceinline__ float fsig(float x) {
    return 0.5f * ftanh(0.5f * x) + 0.5f;
}
__device__ __forceinline__ uint32_t tf32_bits(float x) {
    uint32_t r;
    asm("cvt.rna.tf32.f32 %0, %1;" : "=r"(r) : "f"(x));
    return r;
}
__device__ __forceinline__ float tf32f(float x) {
    return __uint_as_float(tf32_bits(x));
}
// D += A(16x8) * B(8x8), tf32 inputs (bit-passed fp32), fp32 accum.
__device__ __forceinline__ void mma_tf32(float* c,
    uint32_t a0, uint32_t a1, uint32_t a2, uint32_t a3,
    uint32_t b0, uint32_t b1)
{
    asm volatile(
        "mma.sync.aligned.m16n8k8.row.col.f32.tf32.tf32.f32 "
        "{%0,%1,%2,%3}, {%4,%5,%6,%7}, {%8,%9}, {%0,%1,%2,%3};"
        : "+f"(c[0]), "+f"(c[1]), "+f"(c[2]), "+f"(c[3])
        : "r"(a0), "r"(a1), "r"(a2), "r"(a3), "r"(b0), "r"(b1));
}

// Packed gate-column decode: n' in [0,1024): [IF(512) | GO(512)], col 2u+b.
__device__ __forceinline__ int packed_gate_row(int nprime) {
    const int np = nprime & 511, u = np >> 1, b = np & 1;
    const bool go = nprime >= 512;
    return u + (go ? (b ? 768 : 512) : (b ? 256 : 0));   // rows: i|f|g|o blocks
}

// ---------------------------------------------------------------------------
// Pack kernels (run every launch; one-time scatter/gather, ~tens of us)
// ---------------------------------------------------------------------------
__global__ void __launch_bounds__(1024) pack_gates(
    const float* __restrict__ W_ih, const float* __restrict__ W_hh)
{
    const int idx = blockIdx.x * 1024 + threadIdx.x;   // 128*64*32 = 262144
    const int lane = idx & 31;
    const int kt   = (idx >> 5) & 63;
    const int nt   = idx >> 11;                        // 0..127
    const int npr  = (nt & 63) * 8 + (lane >> 2) + ((nt >= 64) ? 512 : 0);
    const int row  = packed_gate_row(npr);
    const int k0   = kt * 8 + (lane & 3);
    const int k1   = k0 + 4;
    const float v0 = (k0 < 256) ? W_ih[(size_t)row * DCC + k0]
                                : W_hh[(size_t)row * HH + k0 - 256];
    const float v1 = (k1 < 256) ? W_ih[(size_t)row * DCC + k1]
                                : W_hh[(size_t)row * HH + k1 - 256];
    g_WfragGates[idx] = make_float2(tf32f(v0), tf32f(v1));
}

__global__ void __launch_bounds__(1024) pack_h2h(const float* __restrict__ W_h2h)
{
    const int idx = blockIdx.x * 1024 + threadIdx.x;   // 32*32*32 = 32768
    const int lane = idx & 31;
    const int kt   = (idx >> 5) & 31;
    const int nt   = idx >> 10;                        // 0..31
    const int n    = nt * 8 + (lane >> 2);
    const int k0   = kt * 8 + (lane & 3);
    g_WfragH2h[idx] = make_float2(tf32f(W_h2h[n * HH + k0]),
                                  tf32f(W_h2h[n * HH + k0 + 4]));
}

__global__ void __launch_bounds__(1024) pack_oh(
    const float* __restrict__ W_ih,
    const float* __restrict__ b_ih, const float* __restrict__ b_hh)
{
    const int c  = blockIdx.x;        // 0..999
    const int np = threadIdx.x;       // 0..1023
    const int row = packed_gate_row(np);
    g_WohP[(size_t)c * 1024 + np] = W_ih[(size_t)row * DCC + 256 + c];
    if (c == 0) g_biasP[np] = b_ih[row] + b_hh[row];
}

// ---------------------------------------------------------------------------
// NT GEMM 128x128x8, 256 threads, 8x8 micro, double-buffered (unchanged R4).
// ---------------------------------------------------------------------------
__global__ void __launch_bounds__(256) hproj_kernel(
    const float* __restrict__ A, const float* __restrict__ W)
{
    __shared__ float As[2][8][132];
    __shared__ float Ws[2][8][132];
    const int bm = blockIdx.x * 128;
    const int bn = blockIdx.y * 128;
    const int tid = threadIdx.x;
    const int tx = tid & 15, ty = tid >> 4;
    const int lr = tid >> 1;
    const int lk = (tid & 1) * 4;

    const float* arow = A + (size_t)(bm + lr) * DD + lk;
    const float* wrow = W + (size_t)(bn + lr) * DD + lk;

    {
        float4 av = *(const float4*)arow;
        float4 wv = *(const float4*)wrow;
        As[0][lk+0][lr]=av.x; As[0][lk+1][lr]=av.y; As[0][lk+2][lr]=av.z; As[0][lk+3][lr]=av.w;
        Ws[0][lk+0][lr]=wv.x; Ws[0][lk+1][lr]=wv.y; Ws[0][lk+2][lr]=wv.z; Ws[0][lk+3][lr]=wv.w;
    }
    __syncthreads();

    float acc[8][8] = {};
    int p = 0;
    const int KT = DD / 8;
    for (int kt = 0; kt < KT; kt++) {
        float4 nav, nwv;
        const bool more = (kt + 1 < KT);
        if (more) {
            nav = *(const float4*)(arow + (kt + 1) * 8);
            nwv = *(const float4*)(wrow + (kt + 1) * 8);
        }
        #pragma unroll
        for (int kk = 0; kk < 8; kk++) {
            float4 a0 = *(const float4*)&As[p][kk][ty * 8];
            float4 a1 = *(const float4*)&As[p][kk][ty * 8 + 4];
            float4 b0 = *(const float4*)&Ws[p][kk][tx * 8];
            float4 b1 = *(const float4*)&Ws[p][kk][tx * 8 + 4];
            float a[8] = {a0.x,a0.y,a0.z,a0.w,a1.x,a1.y,a1.z,a1.w};
            float b[8] = {b0.x,b0.y,b0.z,b0.w,b1.x,b1.y,b1.z,b1.w};
            #pragma unroll
            for (int i = 0; i < 8; i++)
                #pragma unroll
                for (int j = 0; j < 8; j++)
                    acc[i][j] += a[i] * b[j];
        }
        if (more) {
            const int q = p ^ 1;
            As[q][lk+0][lr]=nav.x; As[q][lk+1][lr]=nav.y; As[q][lk+2][lr]=nav.z; As[q][lk+3][lr]=nav.w;
            Ws[q][lk+0][lr]=nwv.x; Ws[q][lk+1][lr]=nwv.y; Ws[q][lk+2][lr]=nwv.z; Ws[q][lk+3][lr]=nwv.w;
        }
        __syncthreads();
        p ^= 1;
    }
    #pragma unroll
    for (int i = 0; i < 8; i++) {
        float* dst = g_Hproj + (size_t)(bm + ty * 8 + i) * HH + bn + tx * 8;
        *(float4*)dst       = make_float4(acc[i][0], acc[i][1], acc[i][2], acc[i][3]);
        *(float4*)(dst + 4) = make_float4(acc[i][4], acc[i][5], acc[i][6], acc[i][7]);
    }
}

__global__ void __launch_bounds__(256) gen_kernel(
    const float* __restrict__ Wg, const float* __restrict__ bg,
    float* __restrict__ out)
{
    __shared__ float As[2][8][132];
    __shared__ float Ws[2][8][132];
    const int bm = blockIdx.x * 128;
    const int bn = blockIdx.y * 128;
    const int tid = threadIdx.x;
    const int tx = tid & 15, ty = tid >> 4;
    const int lr = tid >> 1;
    const int lk = (tid & 1) * 4;

    const float* arow = g_hidden + (size_t)(bm + lr) * HH + lk;
    const bool wok = (bn + lr < CC);
    const float* wrow = Wg + (size_t)(bn + lr) * HH + lk;

    {
        float4 av = *(const float4*)arow;
        float4 wv = wok ? *(const float4*)wrow : make_float4(0.f,0.f,0.f,0.f);
        As[0][lk+0][lr]=av.x; As[0][lk+1][lr]=av.y; As[0][lk+2][lr]=av.z; As[0][lk+3][lr]=av.w;
        Ws[0][lk+0][lr]=wv.x; Ws[0][lk+1][lr]=wv.y; Ws[0][lk+2][lr]=wv.z; Ws[0][lk+3][lr]=wv.w;
    }
    __syncthreads();

    float acc[8][8] = {};
    int p = 0;
    const int KT = HH / 8;
    for (int kt = 0; kt < KT; kt++) {
        float4 nav, nwv;
        const bool more = (kt + 1 < KT);
        if (more) {
            nav = *(const float4*)(arow + (kt + 1) * 8);
            nwv = wok ? *(const float4*)(wrow + (kt + 1) * 8) : make_float4(0.f,0.f,0.f,0.f);
        }
        #pragma unroll
        for (int kk = 0; kk < 8; kk++) {
            float4 a0 = *(const float4*)&As[p][kk][ty * 8];
            float4 a1 = *(const float4*)&As[p][kk][ty * 8 + 4];
            float4 b0 = *(const float4*)&Ws[p][kk][tx * 8];
            float4 b1 = *(const float4*)&Ws[p][kk][tx * 8 + 4];
            float a[8] = {a0.x,a0.y,a0.z,a0.w,a1.x,a1.y,a1.z,a1.w};
            float b[8] = {b0.x,b0.y,b0.z,b0.w,b1.x,b1.y,b1.z,b1.w};
            #pragma unroll
            for (int i = 0; i < 8; i++)
                #pragma unroll
                for (int j = 0; j < 8; j++)
                    acc[i][j] += a[i] * b[j];
        }
        if (more) {
            const int q = p ^ 1;
            As[q][lk+0][lr]=nav.x; As[q][lk+1][lr]=nav.y; As[q][lk+2][lr]=nav.z; As[q][lk+3][lr]=nav.w;
            Ws[q][lk+0][lr]=nwv.x; Ws[q][lk+1][lr]=nwv.y; Ws[q][lk+2][lr]=nwv.z; Ws[q][lk+3][lr]=nwv.w;
        }
        __syncthreads();
        p ^= 1;
    }
    #pragma unroll
    for (int i = 0; i < 8; i++) {
        const int m = bm + ty * 8 + i;
        #pragma unroll
        for (int j = 0; j < 8; j++) {
            const int nn = bn + tx * 8 + j;
            if (nn < CC) out[(size_t)m * CC + nn] = acc[i][j] + bg[nn];
        }
    }
}

// ---------------------------------------------------------------------------
// Persistent recurrence. 128 CTAs x 512 threads. Gates + h2h via tf32 mma.
// ---------------------------------------------------------------------------
__global__ void __launch_bounds__(512) recur_kernel(
    const float* __restrict__ batch_H, const int* __restrict__ text,
    const float* __restrict__ b_h2h,   const float* __restrict__ W_score)
{
    extern __shared__ float sm[];
    float* sh_x   = sm;                      // 16 x XS: cols [0,256)=ctx, [256,512)=h (tf32)
    float* sh_hp  = sh_x  + MROWS * XS;      // 16 x 256
    float* sh_e   = sh_hp + MROWS * HH;      // 16 x 64
    float* sh_ws  = sh_e  + MROWS * TT;      // 256
    int*   sh_ch  = (int*)(sh_ws + HH);      // 16

    const int tid  = threadIdx.x;
    const int w    = tid >> 5;       // warp 0..15
    const int lane = tid & 31;
    const int g    = lane >> 2;      // fragment row group 0..7
    const int tq   = lane & 3;       // fragment quad col
    const int r0   = blockIdx.x * MROWS;

    for (int i = tid; i < MROWS * XS; i += 512) sh_x[i] = 0.f;
    if (tid < 256) sh_ws[tid] = W_score[tid];

    // persistent LSTM cell state: rows {g, g+8} x units {w*16 + jt*4 + tq}
    float cst0[4] = {0.f, 0.f, 0.f, 0.f};
    float cst1[4] = {0.f, 0.f, 0.f, 0.f};

    // step-invariant h2h biases at this thread's output cols
    float2 bh2h_r[2];
    #pragma unroll
    for (int jt = 0; jt < 2; jt++) {
        const int nc = w * 16 + jt * 8 + 2 * tq;
        bh2h_r[jt] = make_float2(b_h2h[nc], b_h2h[nc + 1]);
    }
    __syncthreads();

    for (int s = 0; s < SS; s++) {
        if (tid < MROWS) sh_ch[tid] = text[(r0 + tid) * SS + s];

        // ---- Stage 1: hp = h @ W_h2h^T + b  (tf32 mma, N=256, K=256) ------
        {
            float accH[2][4];
            #pragma unroll
            for (int jt = 0; jt < 2; jt++) {
                accH[jt][0] = bh2h_r[jt].x; accH[jt][1] = bh2h_r[jt].y;
                accH[jt][2] = bh2h_r[jt].x; accH[jt][3] = bh2h_r[jt].y;
            }
            const float2* bp0 = g_WfragH2h + ((size_t)(w * 2    ) * 32) * 32 + lane;
            const float2* bp1 = g_WfragH2h + ((size_t)(w * 2 + 1) * 32) * 32 + lane;
            #pragma unroll 2
            for (int kt = 0; kt < 32; kt++) {
                const float* xk = sh_x + 256 + kt * 8;
                uint32_t a0 = __float_as_uint(xk[ g      * XS + tq]);
                uint32_t a1 = __float_as_uint(xk[(g + 8) * XS + tq]);
                uint32_t a2 = __float_as_uint(xk[ g      * XS + tq + 4]);
                uint32_t a3 = __float_as_uint(xk[(g + 8) * XS + tq + 4]);
                float2 b0 = bp0[kt * 32];
                float2 b1 = bp1[kt * 32];
                mma_tf32(accH[0], a0, a1, a2, a3,
                         __float_as_uint(b0.x), __float_as_uint(b0.y));
                mma_tf32(accH[1], a0, a1, a2, a3,
                         __float_as_uint(b1.x), __float_as_uint(b1.y));
            }
            #pragma unroll
            for (int jt = 0; jt < 2; jt++) {
                const int nc = w * 16 + jt * 8 + 2 * tq;
                *(float2*)(sh_hp +  g      * HH + nc) = make_float2(accH[jt][0], accH[jt][1]);
                *(float2*)(sh_hp + (g + 8) * HH + nc) = make_float2(accH[jt][2], accH[jt][3]);
            }
        }
        __syncthreads();

        // ---- Stage 2: e[m,t] = Wscore . tanh(Hproj + hp) ------------------
        for (int pb = w * 4; pb < MROWS * TT; pb += 64) {
            float sum[4];
            #pragma unroll
            for (int q = 0; q < 4; q++) sum[q] = 0.f;
            #pragma unroll
            for (int i = 0; i < 2; i++) {
                const int h0 = i * 128 + lane * 4;
                const float4 wv = *(const float4*)(sh_ws + h0);
                #pragma unroll
                for (int q = 0; q < 4; q++) {
                    const int pp = pb + q;
                    const int m = pp >> 6, t = pp & 63;
                    const float4 a = *(const float4*)(g_Hproj +
                        ((size_t)(r0 + m) * TT + t) * HH + h0);
                    const float4 b = *(const float4*)(sh_hp + m * HH + h0);
                    sum[q] += wv.x * ftanh(a.x + b.x) + wv.y * ftanh(a.y + b.y)
                            + wv.z * ftanh(a.z + b.z) + wv.w * ftanh(a.w + b.w);
                }
            }
            #pragma unroll
            for (int q = 0; q < 4; q++) {
                float sq = sum[q];
                #pragma unroll
                for (int o = 16; o > 0; o >>= 1)
                    sq += __shfl_xor_sync(0xffffffffu, sq, o);
                if (lane == 0) sh_e[pb + q] = sq;
            }
        }
        __syncthreads();

        // ---- Stage 3: softmax over t, 1 row per warp ----------------------
        {
            const int m = w;
            float e0 = sh_e[m * TT + lane];
            float e1 = sh_e[m * TT + 32 + lane];
            float mx = fmaxf(e0, e1);
            #pragma unroll
            for (int o = 16; o > 0; o >>= 1)
                mx = fmaxf(mx, __shfl_xor_sync(0xffffffffu, mx, o));
            float x0 = __expf(e0 - mx), x1 = __expf(e1 - mx);
            float sume = x0 + x1;
            #pragma unroll
            for (int o = 16; o > 0; o >>= 1)
                sume += __shfl_xor_sync(0xffffffffu, sume, o);
            float inv = __frcp_rn(sume);
            sh_e[m * TT + lane]      = x0 * inv;
            sh_e[m * TT + 32 + lane] = x1 * inv;
        }
        __syncthreads();

        // ---- Stage 4: ctx[m,d] = sum_t alpha[m,t]*batch_H[m,t,d] (tf32) ---
        {
            const int dg = tid & 63;
            const int mg = tid >> 6;
            #pragma unroll
            for (int mi = 0; mi < 2; mi++) {
                const int m = mg * 2 + mi;
                const float* bh = batch_H + ((size_t)(r0 + m) * TT) * DD + dg * 4;
                float4 acc = make_float4(0.f, 0.f, 0.f, 0.f);
                #pragma unroll 8
                for (int t = 0; t < TT; t++) {
                    const float a  = sh_e[m * TT + t];
                    const float4 v = *(const float4*)(bh + (size_t)t * DD);
                    acc.x += a * v.x; acc.y += a * v.y;
                    acc.z += a * v.z; acc.w += a * v.w;
                }
                float4 r;
                r.x = __uint_as_float(tf32_bits(acc.x));
                r.y = __uint_as_float(tf32_bits(acc.y));
                r.z = __uint_as_float(tf32_bits(acc.z));
                r.w = __uint_as_float(tf32_bits(acc.w));
                *(float4*)(sh_x + m * XS + dg * 4) = r;
            }
        }
        __syncthreads();

        // ---- Stage 5: gates (tf32 mma, N=1024, K=512) + LSTM --------------
        {
            const int chg  = sh_ch[g];
            const int chg8 = sh_ch[g + 8];
            float accIF[4][4], accGO[4][4];
            #pragma unroll
            for (int jt = 0; jt < 4; jt++) {
                const int nIF = w * 32 + jt * 8 + 2 * tq;
                const float2 bIF = *(const float2*)(g_biasP + nIF);
                const float2 bGO = *(const float2*)(g_biasP + 512 + nIF);
                const float2 oIg  = *(const float2*)(g_WohP + (size_t)chg  * 1024 + nIF);
                const float2 oIg8 = *(const float2*)(g_WohP + (size_t)chg8 * 1024 + nIF);
                const float2 oGg  = *(const float2*)(g_WohP + (size_t)chg  * 1024 + 512 + nIF);
                const float2 oGg8 = *(const float2*)(g_WohP + (size_t)chg8 * 1024 + 512 + nIF);
                accIF[jt][0] = bIF.x + oIg.x;  accIF[jt][1] = bIF.y + oIg.y;
                accIF[jt][2] = bIF.x + oIg8.x; accIF[jt][3] = bIF.y + oIg8.y;
                accGO[jt][0] = bGO.x + oGg.x;  accGO[jt][1] = bGO.y + oGg.y;
                accGO[jt][2] = bGO.x + oGg8.x; accGO[jt][3] = bGO.y + oGg8.y;
            }
            const float2* bIFp = g_WfragGates + (size_t)(w * 4)      * 64 * 32 + lane;
            const float2* bGOp = g_WfragGates + (size_t)(64 + w * 4) * 64 * 32 + lane;
            #pragma unroll 2
            for (int kt = 0; kt < 64; kt++) {
                const float* xk = sh_x + kt * 8;
                uint32_t a0 = __float_as_uint(xk[ g      * XS + tq]);
                uint32_t a1 = __float_as_uint(xk[(g + 8) * XS + tq]);
                uint32_t a2 = __float_as_uint(xk[ g      * XS + tq + 4]);
                uint32_t a3 = __float_as_uint(xk[(g + 8) * XS + tq + 4]);
                #pragma unroll
                for (int jt = 0; jt < 4; jt++) {
                    const float2 bv = bIFp[(jt * 64 + kt) * 32];
                    mma_tf32(accIF[jt], a0, a1, a2, a3,
                             __float_as_uint(bv.x), __float_as_uint(bv.y));
                    const float2 bw = bGOp[(jt * 64 + kt) * 32];
                    mma_tf32(accGO[jt], a0, a1, a2, a3,
                             __float_as_uint(bw.x), __float_as_uint(bw.y));
                }
            }
            __syncthreads();   // all sh_x reads done before h overwrite
            #pragma unroll
            for (int jt = 0; jt < 4; jt++) {
                const int u = w * 16 + jt * 4 + tq;
                {   // row g: (c0,c1)=(i,f), GO (c0,c1)=(g,o)
                    const float cnew = fsig(accIF[jt][1]) * cst0[jt]
                                     + fsig(accIF[jt][0]) * ftanh(accGO[jt][0]);
                    cst0[jt] = cnew;
                    const float hv = fsig(accGO[jt][1]) * ftanh(cnew);
                    g_hidden[((size_t)(r0 + g) * SS + s) * HH + u] = hv;
                    sh_x[g * XS + 256 + u] = __uint_as_float(tf32_bits(hv));
                }
                {   // row g+8: (c2,c3)
                    const float cnew = fsig(accIF[jt][3]) * cst1[jt]
                                     + fsig(accIF[jt][2]) * ftanh(accGO[jt][2]);
                    cst1[jt] = cnew;
                    const float hv = fsig(accGO[jt][3]) * ftanh(cnew);
                    g_hidden[((size_t)(r0 + g + 8) * SS + s) * HH + u] = hv;
                    sh_x[(g + 8) * XS + 256 + u] = __uint_as_float(tf32_bits(hv));
                }
            }
        }
        __syncthreads();
    }
}

// ---------------------------------------------------------------------------
extern "C" void kernel_launch(void* const* d_in, const int* in_sizes, int n_in,
                              void* d_out, int out_size)
{
    const float* batch_H = (const float*)d_in[0];
    const int*   text    = (const int*)  d_in[1];
    const float* W_i2h   = (const float*)d_in[2];
    const float* W_h2h   = (const float*)d_in[3];
    const float* b_h2h   = (const float*)d_in[4];
    const float* W_score = (const float*)d_in[5];
    const float* W_ih    = (const float*)d_in[6];
    const float* W_hh    = (const float*)d_in[7];
    const float* b_ih    = (const float*)d_in[8];
    const float* b_hh    = (const float*)d_in[9];
    const float* W_gen   = (const float*)d_in[10];
    const float* b_gen   = (const float*)d_in[11];
    float* out = (float*)d_out;

    pack_gates<<<256, 1024>>>(W_ih, W_hh);
    pack_h2h<<<32, 1024>>>(W_h2h);
    pack_oh<<<1000, 1024>>>(W_ih, b_ih, b_hh);

    hproj_kernel<<<dim3((BB * TT) / 128, HH / 128), 256>>>(batch_H, W_i2h);

    const int smem_bytes = (MROWS * XS + MROWS * HH + MROWS * TT + HH) * 4 + MROWS * 4;
    cudaFuncSetAttribute(recur_kernel, cudaFuncAttributeMaxDynamicSharedMemorySize,
                         smem_bytes);
    recur_kernel<<<BB / MROWS, 512, smem_bytes>>>(batch_H, text, b_h2h, W_score);

    gen_kernel<<<dim3((BB * SS) / 128, (CC + 127) / 128), 256>>>(W_gen, b_gen, out);
}